// round 10
// baseline (speedup 1.0000x reference)
#include <cuda_runtime.h>
#include <cuda_fp16.h>
#include <cstdint>

// ScaledDotProductAttention B=8, S=2048, D=1024 fp32.
// HMMA fp16 1-pass both GEMMs; fused exp epilogue + fused 1/rowsum normalization.
// R10: 64x64 warp tiles (ratio 4.0) + 2-stage/1-sync pipe + 3 CTAs/SM (12 warps).

namespace {
constexpr int BN = 8, S_ = 2048, D_ = 1024;
constexpr float SCALE = 0.03125f;          // D^-0.5
constexpr float NEGV  = -1000000000.0f;

constexpr int TM = 128, TN = 128, TK = 64;
constexpr int NT = 128;                                  // threads per CTA
constexpr uint32_t BUF_B   = 16384;                      // one 128x64 fp16 tile
constexpr uint32_t STAGE_B = 2 * BUF_B;                  // A,B
constexpr uint32_t PIPE_B  = 2 * STAGE_B;                // 65536 (2 stages)
constexpr uint32_t SMEM_G1 = PIPE_B + 512 + 1024;        // + mask row + rowsum buf
constexpr uint32_t SMEM_G2 = PIPE_B + 512;               // + inv row buf
}  // namespace

// ------------------------- scratch (device globals) -------------------------
__device__ __align__(128) __half g_qh[(size_t)BN * S_ * D_];
__device__ __align__(128) __half g_kh[(size_t)BN * S_ * D_];
__device__ __align__(128) __half g_vt[(size_t)BN * D_ * S_];   // V^T [b][d][s]
__device__ __align__(128) __half g_p [(size_t)BN * S_ * S_];   // unnormalized exp P~
__device__ __align__(128) float  g_ps[(size_t)BN * S_ * 16];   // row partial sums

// ------------------------------- helpers ------------------------------------
__device__ __forceinline__ uint32_t smem_u32(const void* p) {
    uint32_t a;
    asm("{ .reg .u64 t; cvta.to.shared.u64 t, %1; cvt.u32.u64 %0, t; }"
        : "=r"(a) : "l"(p));
    return a;
}

#define LDSM4(r, addr) \
    asm volatile("ldmatrix.sync.aligned.m8n8.x4.shared.b16 {%0,%1,%2,%3}, [%4];" \
        : "=r"((r)[0]), "=r"((r)[1]), "=r"((r)[2]), "=r"((r)[3]) : "r"(addr))

#define MMA_F16(d, a, b0, b1) \
    asm volatile("mma.sync.aligned.m16n8k16.row.col.f32.f16.f16.f32 " \
        "{%0,%1,%2,%3}, {%4,%5,%6,%7}, {%8,%9}, {%0,%1,%2,%3};" \
        : "+f"((d)[0]), "+f"((d)[1]), "+f"((d)[2]), "+f"((d)[3]) \
        : "r"((a)[0]), "r"((a)[1]), "r"((a)[2]), "r"((a)[3]), "r"(b0), "r"(b1))

#define CP_ASYNC16(dst, src) \
    asm volatile("cp.async.cg.shared.global [%0], [%1], 16;" :: "r"(dst), "l"(src))
#define CP_COMMIT()  asm volatile("cp.async.commit_group;" ::: "memory")
#define CP_WAIT(n)   asm volatile("cp.async.wait_group %0;" :: "n"(n) : "memory")

__device__ __forceinline__ uint2 pack4(const uint16_t* h) {
    return make_uint2((uint32_t)h[0] | ((uint32_t)h[1] << 16),
                      (uint32_t)h[2] | ((uint32_t)h[3] << 16));
}

// --------------------------- convert kernels --------------------------------
__global__ void __launch_bounds__(256) conv_h_kernel(
    const float* __restrict__ src, __half* __restrict__ dst) {
    size_t e0 = ((size_t)blockIdx.x * 256 + threadIdx.x) * 4;
    float4 val = *reinterpret_cast<const float4*>(src + e0);
    uint16_t h[4];
    h[0] = __half_as_ushort(__float2half_rn(val.x));
    h[1] = __half_as_ushort(__float2half_rn(val.y));
    h[2] = __half_as_ushort(__float2half_rn(val.z));
    h[3] = __half_as_ushort(__float2half_rn(val.w));
    *reinterpret_cast<uint2*>(dst + e0) = pack4(h);
}

__global__ void __launch_bounds__(256) conv_v_kernel(const float* __restrict__ v) {
    __shared__ float tile[64][68];
    int b  = blockIdx.y;
    int st = blockIdx.x >> 4;
    int dt = blockIdx.x & 15;
    int tid = threadIdx.x;
    int i0 = tid >> 4, j4 = (tid & 15) * 4;
#pragma unroll
    for (int r = 0; r < 4; ++r) {
        int i = i0 + r * 16;
        float4 val = *reinterpret_cast<const float4*>(
            v + ((size_t)b * S_ + st * 64 + i) * D_ + dt * 64 + j4);
        tile[i][j4 + 0] = val.x; tile[i][j4 + 1] = val.y;
        tile[i][j4 + 2] = val.z; tile[i][j4 + 3] = val.w;
    }
    __syncthreads();
#pragma unroll
    for (int r = 0; r < 4; ++r) {
        int dl_ = i0 + r * 16;
        uint16_t h[4];
#pragma unroll
        for (int c = 0; c < 4; ++c)
            h[c] = __half_as_ushort(__float2half_rn(tile[j4 + c][dl_]));
        size_t off = ((size_t)b * D_ + dt * 64 + dl_) * S_ + st * 64 + j4;
        *reinterpret_cast<uint2*>(g_vt + off) = pack4(h);
    }
}

// ------------------ GEMM1: P~ = exp(QK^T*SCALE + mask) ----------------------
__global__ void __launch_bounds__(NT, 3)
gemm1_kernel(const __half* __restrict__ Ah, const __half* __restrict__ Bh,
             const float* __restrict__ mask) {
    extern __shared__ __align__(1024) char smg[];
    const uint32_t smb = smem_u32(smg);
    float* smmask = (float*)(smg + PIPE_B);
    float (*smsum)[2] = (float(*)[2])(smg + PIPE_B + 512);  // [128][2]

    const int tid = threadIdx.x;
    const int mt = blockIdx.x, nt = blockIdx.y, b = blockIdx.z;
    const int warp = tid >> 5, lane = tid & 31;
    const int wm = warp & 1, wn = warp >> 1;   // 2x2 warp grid, 64x64 tiles
    const int lrow = lane & 15;
    const int lh16 = (lane >> 4) << 4;
    const int r7 = (lane & 7) << 4;
    constexpr int NC = D_ / TK;  // 16

    const int drow = tid >> 3, cc = tid & 7;
    const uint32_t dstoff0 = (uint32_t)(drow * 128 + ((cc ^ (drow & 7)) << 4));
    const __half* gA = Ah + ((size_t)b * S_ + mt * TM + drow) * D_ + cc * 8;
    const __half* gB = Bh + ((size_t)b * S_ + nt * TN + drow) * D_ + cc * 8;

    smmask[tid] = mask[(size_t)b * S_ + nt * TN + tid] * NEGV;

    uint32_t sload = 0;
    auto issue = [&]() {
        uint32_t da = smb + sload + dstoff0;
#pragma unroll
        for (int i = 0; i < 8; ++i) {
            CP_ASYNC16(da + i * 2048,         gA + i * 16 * D_);
            CP_ASYNC16(da + BUF_B + i * 2048, gB + i * 16 * D_);
        }
        CP_COMMIT();
        gA += TK; gB += TK;
        sload ^= STAGE_B;
    };

    float acc[4][8][4];
#pragma unroll
    for (int i = 0; i < 4; ++i)
#pragma unroll
        for (int n = 0; n < 8; ++n)
#pragma unroll
            for (int r = 0; r < 4; ++r) acc[i][n][r] = 0.f;

    issue();

    const uint32_t cA = (uint32_t)((wm * 64 + lrow) * 128);
    const uint32_t cB = (uint32_t)(BUF_B + (wn * 64 + lrow) * 128);

    uint32_t scomp = 0;
#pragma unroll 1
    for (int c = 0; c < NC; ++c) {
        CP_WAIT(0);
        __syncthreads();         // buffer (c+1)&1 fully consumed by all warps
        if (c + 1 < NC) issue();

        const uint32_t uA0 = smb + scomp + cA;
        const uint32_t uB0 = smb + scomp + cB;
        scomp ^= STAGE_B;

#pragma unroll
        for (int ks = 0; ks < 4; ++ks) {
            const uint32_t kxr = (uint32_t)((ks * 32 + lh16) ^ r7);
            uint32_t ah[4][4], bh[2][4];
#pragma unroll
            for (int i = 0; i < 4; ++i) LDSM4(ah[i], uA0 + i * 2048 + kxr);
            LDSM4(bh[0], uB0 + kxr);
            LDSM4(bh[1], uB0 + 2048 + kxr);
#pragma unroll
            for (int i = 0; i < 4; ++i)
#pragma unroll
                for (int n = 0; n < 4; ++n) {
                    int j = n >> 1, s = n & 1;
                    MMA_F16(acc[i][n], ah[i], bh[j][s], bh[j][s + 2]);
                }
            LDSM4(bh[0], uB0 + 2 * 2048 + kxr);
            LDSM4(bh[1], uB0 + 3 * 2048 + kxr);
#pragma unroll
            for (int i = 0; i < 4; ++i)
#pragma unroll
                for (int n = 4; n < 8; ++n) {
                    int j = (n - 4) >> 1, s = n & 1;
                    MMA_F16(acc[i][n], ah[i], bh[j][s], bh[j][s + 2]);
                }
        }
    }

    // ---- epilogue: e = exp(acc*SCALE + mask), write fp16, reduce row sums ----
    const int rloc = wm * 64 + (lane >> 2);
    const int r0 = mt * TM + rloc;
    const int cl0 = wn * 64 + (lane & 3) * 2;
#pragma unroll
    for (int i = 0; i < 4; ++i) {
        float sum_lo = 0.f, sum_hi = 0.f;
#pragma unroll
        for (int n = 0; n < 8; ++n) {
            int cl = cl0 + n * 8;
            float mk0 = smmask[cl], mk1 = smmask[cl + 1];
            float e0 = __expf(acc[i][n][0] * SCALE + mk0);
            float e1 = __expf(acc[i][n][1] * SCALE + mk1);
            float e2 = __expf(acc[i][n][2] * SCALE + mk0);
            float e3 = __expf(acc[i][n][3] * SCALE + mk1);
            sum_lo += e0 + e1;
            sum_hi += e2 + e3;
            size_t rowa = (size_t)(b * S_ + r0 + i * 16) * S_ + nt * TN + cl;
            size_t rowb = rowa + (size_t)8 * S_;
            *reinterpret_cast<__half2*>(g_p + rowa) = __floats2half2_rn(e0, e1);
            *reinterpret_cast<__half2*>(g_p + rowb) = __floats2half2_rn(e2, e3);
        }
#pragma unroll
        for (int o = 1; o < 4; o <<= 1) {
            sum_lo += __shfl_xor_sync(~0u, sum_lo, o);
            sum_hi += __shfl_xor_sync(~0u, sum_hi, o);
        }
        if ((lane & 3) == 0) {
            smsum[rloc + i * 16][wn]     = sum_lo;
            smsum[rloc + i * 16 + 8][wn] = sum_hi;
        }
    }
    __syncthreads();
    {
        float s = smsum[tid][0] + smsum[tid][1];
        g_ps[((size_t)(b * S_ + mt * TM + tid)) * 16 + nt] = s;
    }
}

// ------------- GEMM2: out = (P~ @ V) * (1/rowsum)  (1-pass fp16) -------------
__global__ void __launch_bounds__(NT, 3)
gemm2_kernel(const __half* __restrict__ A, const __half* __restrict__ Bt,
             float* __restrict__ Cp) {
    extern __shared__ __align__(1024) char smg[];
    const uint32_t smb = smem_u32(smg);
    float* sminv = (float*)(smg + PIPE_B);  // [128]

    const int tid = threadIdx.x;
    const int mt = blockIdx.x, nt = blockIdx.y, b = blockIdx.z;
    const int warp = tid >> 5, lane = tid & 31;
    const int wm = warp & 1, wn = warp >> 1;
    const int lrow = lane & 15;
    const int lh16 = (lane >> 4) << 4;
    const int r7 = (lane & 7) << 4;
    constexpr int NC = S_ / TK;  // 32

    const int drow = tid >> 3, cc = tid & 7;
    const uint32_t dstoff0 = (uint32_t)(drow * 128 + ((cc ^ (drow & 7)) << 4));
    const __half* gA = A  + ((size_t)b * S_ + mt * TM + drow) * S_ + cc * 8;
    const __half* gB = Bt + ((size_t)b * D_ + nt * TN + drow) * S_ + cc * 8;

    {
        const float* ps = g_ps + ((size_t)(b * S_ + mt * TM + tid)) * 16;
        float s = 0.f;
#pragma unroll
        for (int j = 0; j < 16; ++j) s += ps[j];
        sminv[tid] = 1.0f / s;
    }

    uint32_t sload = 0;
    auto issue = [&]() {
        uint32_t da = smb + sload + dstoff0;
#pragma unroll
        for (int i = 0; i < 8; ++i) {
            CP_ASYNC16(da + i * 2048,         gA + i * 16 * S_);
            CP_ASYNC16(da + BUF_B + i * 2048, gB + i * 16 * S_);
        }
        CP_COMMIT();
        gA += TK; gB += TK;
        sload ^= STAGE_B;
    };

    float acc[4][8][4];
#pragma unroll
    for (int i = 0; i < 4; ++i)
#pragma unroll
        for (int n = 0; n < 8; ++n)
#pragma unroll
            for (int r = 0; r < 4; ++r) acc[i][n][r] = 0.f;

    issue();

    const uint32_t cA = (uint32_t)((wm * 64 + lrow) * 128);
    const uint32_t cB = (uint32_t)(BUF_B + (wn * 64 + lrow) * 128);

    uint32_t scomp = 0;
#pragma unroll 1
    for (int c = 0; c < NC; ++c) {
        CP_WAIT(0);
        __syncthreads();
        if (c + 1 < NC) issue();

        const uint32_t uA0 = smb + scomp + cA;
        const uint32_t uB0 = smb + scomp + cB;
        scomp ^= STAGE_B;

#pragma unroll
        for (int ks = 0; ks < 4; ++ks) {
            const uint32_t kxr = (uint32_t)((ks * 32 + lh16) ^ r7);
            uint32_t ah[4][4], bh[2][4];
#pragma unroll
            for (int i = 0; i < 4; ++i) LDSM4(ah[i], uA0 + i * 2048 + kxr);
            LDSM4(bh[0], uB0 + kxr);
            LDSM4(bh[1], uB0 + 2048 + kxr);
#pragma unroll
            for (int i = 0; i < 4; ++i)
#pragma unroll
                for (int n = 0; n < 4; ++n) {
                    int j = n >> 1, s = n & 1;
                    MMA_F16(acc[i][n], ah[i], bh[j][s], bh[j][s + 2]);
                }
            LDSM4(bh[0], uB0 + 2 * 2048 + kxr);
            LDSM4(bh[1], uB0 + 3 * 2048 + kxr);
#pragma unroll
            for (int i = 0; i < 4; ++i)
#pragma unroll
                for (int n = 4; n < 8; ++n) {
                    int j = (n - 4) >> 1, s = n & 1;
                    MMA_F16(acc[i][n], ah[i], bh[j][s], bh[j][s + 2]);
                }
        }
    }

    const int rloc = wm * 64 + (lane >> 2);
    const int r0 = mt * TM + rloc;
    const int cl0 = wn * 64 + (lane & 3) * 2;
#pragma unroll
    for (int i = 0; i < 4; ++i) {
        float inv_lo = sminv[rloc + i * 16];
        float inv_hi = sminv[rloc + i * 16 + 8];
#pragma unroll
        for (int n = 0; n < 8; ++n) {
            int col = nt * TN + cl0 + n * 8;
            size_t rowa = (size_t)(b * S_ + r0 + i * 16) * D_ + col;
            size_t rowb = rowa + (size_t)8 * D_;
            *reinterpret_cast<float2*>(Cp + rowa) =
                make_float2(acc[i][n][0] * inv_lo, acc[i][n][1] * inv_lo);
            *reinterpret_cast<float2*>(Cp + rowb) =
                make_float2(acc[i][n][2] * inv_hi, acc[i][n][3] * inv_hi);
        }
    }
}

// --------------------------------- launch -----------------------------------
extern "C" void kernel_launch(void* const* d_in, const int* in_sizes, int n_in,
                              void* d_out, int out_size) {
    const float* q    = (const float*)d_in[0];
    const float* k    = (const float*)d_in[1];
    const float* v    = (const float*)d_in[2];
    const float* mask = (const float*)d_in[3];
    float* out = (float*)d_out;

    cudaFuncSetAttribute(gemm1_kernel,
                         cudaFuncAttributeMaxDynamicSharedMemorySize, SMEM_G1);
    cudaFuncSetAttribute(gemm2_kernel,
                         cudaFuncAttributeMaxDynamicSharedMemorySize, SMEM_G2);

    __half *qh, *kh, *vt, *p;
    cudaGetSymbolAddress((void**)&qh, g_qh);
    cudaGetSymbolAddress((void**)&kh, g_kh);
    cudaGetSymbolAddress((void**)&vt, g_vt);
    cudaGetSymbolAddress((void**)&p,  g_p);

    conv_h_kernel<<<16384, 256>>>(q, qh);
    conv_h_kernel<<<16384, 256>>>(k, kh);
    conv_v_kernel<<<dim3(512, 8), 256>>>(v);

    gemm1_kernel<<<dim3(16, 16, 8), NT, SMEM_G1>>>(qh, kh, mask);
    gemm2_kernel<<<dim3(16, 8, 8), NT, SMEM_G2>>>(p, vt, out);
}

// round 11
// speedup vs baseline: 1.1002x; 1.1002x over previous
#include <cuda_runtime.h>
#include <cuda_fp16.h>
#include <cstdint>

// ScaledDotProductAttention B=8, S=2048, D=1024 fp32.
// HMMA fp16 1-pass both GEMMs; fused exp epilogue + fused 1/rowsum normalization.
// R11: R9 base (64x64 warp tiles, 3-stage pipe, 2 CTAs/SM) + fragment
//      double-buffering (hide LDSM latency under MMAs) + fused convert kernel.

namespace {
constexpr int BN = 8, S_ = 2048, D_ = 1024;
constexpr float SCALE = 0.03125f;          // D^-0.5
constexpr float NEGV  = -1000000000.0f;

constexpr int TM = 128, TN = 128, TK = 64;
constexpr int NT = 128;                                  // threads per CTA
constexpr uint32_t BUF_B   = 16384;                      // one 128x64 fp16 tile
constexpr uint32_t STAGE_B = 2 * BUF_B;                  // A,B
constexpr uint32_t PIPE_B  = 3 * STAGE_B;                // 98304
constexpr uint32_t SMEM_G1 = PIPE_B + 512 + 1024;        // + mask row + rowsum buf
constexpr uint32_t SMEM_G2 = PIPE_B + 512;               // + inv row buf
}  // namespace

// ------------------------- scratch (device globals) -------------------------
__device__ __align__(128) __half g_qh[(size_t)BN * S_ * D_];
__device__ __align__(128) __half g_kh[(size_t)BN * S_ * D_];
__device__ __align__(128) __half g_vt[(size_t)BN * D_ * S_];   // V^T [b][d][s]
__device__ __align__(128) __half g_p [(size_t)BN * S_ * S_];   // unnormalized exp P~
__device__ __align__(128) float  g_ps[(size_t)BN * S_ * 16];   // row partial sums

// ------------------------------- helpers ------------------------------------
__device__ __forceinline__ uint32_t smem_u32(const void* p) {
    uint32_t a;
    asm("{ .reg .u64 t; cvta.to.shared.u64 t, %1; cvt.u32.u64 %0, t; }"
        : "=r"(a) : "l"(p));
    return a;
}

#define LDSM4(r, addr) \
    asm volatile("ldmatrix.sync.aligned.m8n8.x4.shared.b16 {%0,%1,%2,%3}, [%4];" \
        : "=r"((r)[0]), "=r"((r)[1]), "=r"((r)[2]), "=r"((r)[3]) : "r"(addr))

#define MMA_F16(d, a, b0, b1) \
    asm volatile("mma.sync.aligned.m16n8k16.row.col.f32.f16.f16.f32 " \
        "{%0,%1,%2,%3}, {%4,%5,%6,%7}, {%8,%9}, {%0,%1,%2,%3};" \
        : "+f"((d)[0]), "+f"((d)[1]), "+f"((d)[2]), "+f"((d)[3]) \
        : "r"((a)[0]), "r"((a)[1]), "r"((a)[2]), "r"((a)[3]), "r"(b0), "r"(b1))

#define CP_ASYNC16(dst, src) \
    asm volatile("cp.async.cg.shared.global [%0], [%1], 16;" :: "r"(dst), "l"(src))
#define CP_COMMIT()  asm volatile("cp.async.commit_group;" ::: "memory")
#define CP_WAIT(n)   asm volatile("cp.async.wait_group %0;" :: "n"(n) : "memory")

__device__ __forceinline__ uint2 pack4(const uint16_t* h) {
    return make_uint2((uint32_t)h[0] | ((uint32_t)h[1] << 16),
                      (uint32_t)h[2] | ((uint32_t)h[3] << 16));
}

// --------------------------- fused convert kernel ----------------------------
// blocks [0,16384): Q -> fp16 ; [16384,32768): K -> fp16 ;
// [32768,36864): V[b][s][d] -> V^T[b][d][s] fp16.
__global__ void __launch_bounds__(256) conv_all_kernel(
    const float* __restrict__ q, const float* __restrict__ k,
    const float* __restrict__ v) {
    __shared__ float tile[64][68];
    const int bx = blockIdx.x;
    const int tid = threadIdx.x;

    if (bx < 32768) {
        const float* src = (bx < 16384) ? q : k;
        __half* dst = (bx < 16384) ? g_qh : g_kh;
        size_t e0 = ((size_t)(bx & 16383) * 256 + tid) * 4;
        float4 val = *reinterpret_cast<const float4*>(src + e0);
        uint16_t h[4];
        h[0] = __half_as_ushort(__float2half_rn(val.x));
        h[1] = __half_as_ushort(__float2half_rn(val.y));
        h[2] = __half_as_ushort(__float2half_rn(val.z));
        h[3] = __half_as_ushort(__float2half_rn(val.w));
        *reinterpret_cast<uint2*>(dst + e0) = pack4(h);
        return;
    }

    const int id = bx - 32768;          // 0..4095
    const int b  = id >> 9;
    const int rest = id & 511;
    const int st = rest >> 4;           // s tile (0..31)
    const int dt = rest & 15;           // d tile (0..15)
    const int i0 = tid >> 4, j4 = (tid & 15) * 4;
#pragma unroll
    for (int r = 0; r < 4; ++r) {
        int i = i0 + r * 16;
        float4 val = *reinterpret_cast<const float4*>(
            v + ((size_t)b * S_ + st * 64 + i) * D_ + dt * 64 + j4);
        tile[i][j4 + 0] = val.x; tile[i][j4 + 1] = val.y;
        tile[i][j4 + 2] = val.z; tile[i][j4 + 3] = val.w;
    }
    __syncthreads();
#pragma unroll
    for (int r = 0; r < 4; ++r) {
        int dl_ = i0 + r * 16;
        uint16_t h[4];
#pragma unroll
        for (int c = 0; c < 4; ++c)
            h[c] = __half_as_ushort(__float2half_rn(tile[j4 + c][dl_]));
        size_t off = ((size_t)b * D_ + dt * 64 + dl_) * S_ + st * 64 + j4;
        *reinterpret_cast<uint2*>(g_vt + off) = pack4(h);
    }
}

// ------------------ GEMM1: P~ = exp(QK^T*SCALE + mask) ----------------------
__global__ void __launch_bounds__(NT, 2)
gemm1_kernel(const __half* __restrict__ Ah, const __half* __restrict__ Bh,
             const float* __restrict__ mask) {
    extern __shared__ __align__(1024) char smg[];
    const uint32_t smb = smem_u32(smg);
    float* smmask = (float*)(smg + PIPE_B);
    float (*smsum)[2] = (float(*)[2])(smg + PIPE_B + 512);  // [128][2]

    const int tid = threadIdx.x;
    const int mt = blockIdx.x, nt = blockIdx.y, b = blockIdx.z;
    const int warp = tid >> 5, lane = tid & 31;
    const int wm = warp & 1, wn = warp >> 1;   // 2x2 warp grid, 64x64 tiles
    const int lrow = lane & 15;
    const int lh16 = (lane >> 4) << 4;
    const int r7 = (lane & 7) << 4;
    constexpr int NC = D_ / TK;  // 16

    const int drow = tid >> 3, cc = tid & 7;
    const uint32_t dstoff0 = (uint32_t)(drow * 128 + ((cc ^ (drow & 7)) << 4));
    const __half* gA = Ah + ((size_t)b * S_ + mt * TM + drow) * D_ + cc * 8;
    const __half* gB = Bh + ((size_t)b * S_ + nt * TN + drow) * D_ + cc * 8;

    smmask[tid] = mask[(size_t)b * S_ + nt * TN + tid] * NEGV;

    uint32_t sload = 0;
    auto issue = [&]() {
        uint32_t da = smb + sload + dstoff0;
#pragma unroll
        for (int i = 0; i < 8; ++i) {
            CP_ASYNC16(da + i * 2048,         gA + i * 16 * D_);
            CP_ASYNC16(da + BUF_B + i * 2048, gB + i * 16 * D_);
        }
        CP_COMMIT();
        gA += TK; gB += TK;
        sload += STAGE_B; if (sload == PIPE_B) sload = 0;
    };

    float acc[4][8][4];
#pragma unroll
    for (int i = 0; i < 4; ++i)
#pragma unroll
        for (int n = 0; n < 8; ++n)
#pragma unroll
            for (int r = 0; r < 4; ++r) acc[i][n][r] = 0.f;

    issue();
    issue();

    const uint32_t cA = (uint32_t)((wm * 64 + lrow) * 128);
    const uint32_t cB = (uint32_t)(BUF_B + (wn * 64 + lrow) * 128);

    uint32_t scomp = 0;
#pragma unroll 1
    for (int c = 0; c < NC; ++c) {
        if (c + 1 < NC) CP_WAIT(1);
        else            CP_WAIT(0);
        __syncthreads();
        if (c + 2 < NC) issue();

        const uint32_t uA0 = smb + scomp + cA;
        const uint32_t uB0 = smb + scomp + cB;
        scomp += STAGE_B; if (scomp == PIPE_B) scomp = 0;

        // fragment double-buffer: prefetch ks+1 while issuing ks's MMAs
        uint32_t ah[2][4][4], bh[2][4][4];
        {
            const uint32_t kxr0 = (uint32_t)(lh16 ^ r7);
#pragma unroll
            for (int i = 0; i < 4; ++i) LDSM4(ah[0][i], uA0 + i * 2048 + kxr0);
#pragma unroll
            for (int j = 0; j < 4; ++j) LDSM4(bh[0][j], uB0 + j * 2048 + kxr0);
        }
#pragma unroll
        for (int ks = 0; ks < 4; ++ks) {
            const int cur = ks & 1, nxt = cur ^ 1;
            if (ks < 3) {
                const uint32_t kxr = (uint32_t)(((ks + 1) * 32 + lh16) ^ r7);
#pragma unroll
                for (int i = 0; i < 4; ++i)
                    LDSM4(ah[nxt][i], uA0 + i * 2048 + kxr);
#pragma unroll
                for (int j = 0; j < 4; ++j)
                    LDSM4(bh[nxt][j], uB0 + j * 2048 + kxr);
            }
#pragma unroll
            for (int i = 0; i < 4; ++i)
#pragma unroll
                for (int n = 0; n < 8; ++n) {
                    int j = n >> 1, s = n & 1;
                    MMA_F16(acc[i][n], ah[cur][i], bh[cur][j][s], bh[cur][j][s + 2]);
                }
        }
    }

    // ---- epilogue: e = exp(acc*SCALE + mask), write fp16, reduce row sums ----
    const int rloc = wm * 64 + (lane >> 2);
    const int r0 = mt * TM + rloc;
    const int cl0 = wn * 64 + (lane & 3) * 2;
#pragma unroll
    for (int i = 0; i < 4; ++i) {
        float sum_lo = 0.f, sum_hi = 0.f;
#pragma unroll
        for (int n = 0; n < 8; ++n) {
            int cl = cl0 + n * 8;
            float mk0 = smmask[cl], mk1 = smmask[cl + 1];
            float e0 = __expf(acc[i][n][0] * SCALE + mk0);
            float e1 = __expf(acc[i][n][1] * SCALE + mk1);
            float e2 = __expf(acc[i][n][2] * SCALE + mk0);
            float e3 = __expf(acc[i][n][3] * SCALE + mk1);
            sum_lo += e0 + e1;
            sum_hi += e2 + e3;
            size_t rowa = (size_t)(b * S_ + r0 + i * 16) * S_ + nt * TN + cl;
            size_t rowb = rowa + (size_t)8 * S_;
            *reinterpret_cast<__half2*>(g_p + rowa) = __floats2half2_rn(e0, e1);
            *reinterpret_cast<__half2*>(g_p + rowb) = __floats2half2_rn(e2, e3);
        }
#pragma unroll
        for (int o = 1; o < 4; o <<= 1) {
            sum_lo += __shfl_xor_sync(~0u, sum_lo, o);
            sum_hi += __shfl_xor_sync(~0u, sum_hi, o);
        }
        if ((lane & 3) == 0) {
            smsum[rloc + i * 16][wn]     = sum_lo;
            smsum[rloc + i * 16 + 8][wn] = sum_hi;
        }
    }
    __syncthreads();
    {
        float s = smsum[tid][0] + smsum[tid][1];
        g_ps[((size_t)(b * S_ + mt * TM + tid)) * 16 + nt] = s;
    }
}

// ------------- GEMM2: out = (P~ @ V) * (1/rowsum)  (1-pass fp16) -------------
__global__ void __launch_bounds__(NT, 2)
gemm2_kernel(const __half* __restrict__ A, const __half* __restrict__ Bt,
             float* __restrict__ Cp) {
    extern __shared__ __align__(1024) char smg[];
    const uint32_t smb = smem_u32(smg);
    float* sminv = (float*)(smg + PIPE_B);  // [128]

    const int tid = threadIdx.x;
    const int mt = blockIdx.x, nt = blockIdx.y, b = blockIdx.z;
    const int warp = tid >> 5, lane = tid & 31;
    const int wm = warp & 1, wn = warp >> 1;
    const int lrow = lane & 15;
    const int lh16 = (lane >> 4) << 4;
    const int r7 = (lane & 7) << 4;
    constexpr int NC = S_ / TK;  // 32

    const int drow = tid >> 3, cc = tid & 7;
    const uint32_t dstoff0 = (uint32_t)(drow * 128 + ((cc ^ (drow & 7)) << 4));
    const __half* gA = A  + ((size_t)b * S_ + mt * TM + drow) * S_ + cc * 8;
    const __half* gB = Bt + ((size_t)b * D_ + nt * TN + drow) * S_ + cc * 8;

    {
        const float* ps = g_ps + ((size_t)(b * S_ + mt * TM + tid)) * 16;
        float s = 0.f;
#pragma unroll
        for (int j = 0; j < 16; ++j) s += ps[j];
        sminv[tid] = 1.0f / s;
    }

    uint32_t sload = 0;
    auto issue = [&]() {
        uint32_t da = smb + sload + dstoff0;
#pragma unroll
        for (int i = 0; i < 8; ++i) {
            CP_ASYNC16(da + i * 2048,         gA + i * 16 * S_);
            CP_ASYNC16(da + BUF_B + i * 2048, gB + i * 16 * S_);
        }
        CP_COMMIT();
        gA += TK; gB += TK;
        sload += STAGE_B; if (sload == PIPE_B) sload = 0;
    };

    float acc[4][8][4];
#pragma unroll
    for (int i = 0; i < 4; ++i)
#pragma unroll
        for (int n = 0; n < 8; ++n)
#pragma unroll
            for (int r = 0; r < 4; ++r) acc[i][n][r] = 0.f;

    issue();
    issue();

    const uint32_t cA = (uint32_t)((wm * 64 + lrow) * 128);
    const uint32_t cB = (uint32_t)(BUF_B + (wn * 64 + lrow) * 128);

    uint32_t scomp = 0;
#pragma unroll 1
    for (int c = 0; c < NC; ++c) {
        if (c + 1 < NC) CP_WAIT(1);
        else            CP_WAIT(0);
        __syncthreads();
        if (c + 2 < NC) issue();

        const uint32_t uA0 = smb + scomp + cA;
        const uint32_t uB0 = smb + scomp + cB;
        scomp += STAGE_B; if (scomp == PIPE_B) scomp = 0;

        uint32_t ah[2][4][4], bh[2][4][4];
        {
            const uint32_t kxr0 = (uint32_t)(lh16 ^ r7);
#pragma unroll
            for (int i = 0; i < 4; ++i) LDSM4(ah[0][i], uA0 + i * 2048 + kxr0);
#pragma unroll
            for (int j = 0; j < 4; ++j) LDSM4(bh[0][j], uB0 + j * 2048 + kxr0);
        }
#pragma unroll
        for (int ks = 0; ks < 4; ++ks) {
            const int cur = ks & 1, nxt = cur ^ 1;
            if (ks < 3) {
                const uint32_t kxr = (uint32_t)(((ks + 1) * 32 + lh16) ^ r7);
#pragma unroll
                for (int i = 0; i < 4; ++i)
                    LDSM4(ah[nxt][i], uA0 + i * 2048 + kxr);
#pragma unroll
                for (int j = 0; j < 4; ++j)
                    LDSM4(bh[nxt][j], uB0 + j * 2048 + kxr);
            }
#pragma unroll
            for (int i = 0; i < 4; ++i)
#pragma unroll
                for (int n = 0; n < 8; ++n) {
                    int j = n >> 1, s = n & 1;
                    MMA_F16(acc[i][n], ah[cur][i], bh[cur][j][s], bh[cur][j][s + 2]);
                }
        }
    }

    const int rloc = wm * 64 + (lane >> 2);
    const int r0 = mt * TM + rloc;
    const int cl0 = wn * 64 + (lane & 3) * 2;
#pragma unroll
    for (int i = 0; i < 4; ++i) {
        float inv_lo = sminv[rloc + i * 16];
        float inv_hi = sminv[rloc + i * 16 + 8];
#pragma unroll
        for (int n = 0; n < 8; ++n) {
            int col = nt * TN + cl0 + n * 8;
            size_t rowa = (size_t)(b * S_ + r0 + i * 16) * D_ + col;
            size_t rowb = rowa + (size_t)8 * D_;
            *reinterpret_cast<float2*>(Cp + rowa) =
                make_float2(acc[i][n][0] * inv_lo, acc[i][n][1] * inv_lo);
            *reinterpret_cast<float2*>(Cp + rowb) =
                make_float2(acc[i][n][2] * inv_hi, acc[i][n][3] * inv_hi);
        }
    }
}

// --------------------------------- launch -----------------------------------
extern "C" void kernel_launch(void* const* d_in, const int* in_sizes, int n_in,
                              void* d_out, int out_size) {
    const float* q    = (const float*)d_in[0];
    const float* k    = (const float*)d_in[1];
    const float* v    = (const float*)d_in[2];
    const float* mask = (const float*)d_in[3];
    float* out = (float*)d_out;

    cudaFuncSetAttribute(gemm1_kernel,
                         cudaFuncAttributeMaxDynamicSharedMemorySize, SMEM_G1);
    cudaFuncSetAttribute(gemm2_kernel,
                         cudaFuncAttributeMaxDynamicSharedMemorySize, SMEM_G2);

    __half *qh, *kh, *vt, *p;
    cudaGetSymbolAddress((void**)&qh, g_qh);
    cudaGetSymbolAddress((void**)&kh, g_kh);
    cudaGetSymbolAddress((void**)&vt, g_vt);
    cudaGetSymbolAddress((void**)&p,  g_p);

    conv_all_kernel<<<36864, 256>>>(q, k, v);

    gemm1_kernel<<<dim3(16, 16, 8), NT, SMEM_G1>>>(qh, kh, mask);
    gemm2_kernel<<<dim3(16, 8, 8), NT, SMEM_G2>>>(p, vt, out);
}

// round 13
// speedup vs baseline: 1.1193x; 1.0173x over previous
#include <cuda_runtime.h>
#include <cuda_fp16.h>
#include <cstdint>

// ScaledDotProductAttention B=8, S=2048, D=1024 fp32.
// HMMA fp16 1-pass both GEMMs; fused exp epilogue + fused 1/rowsum normalization.
// R13: R11 base (64x64 warp tiles, 3-stage wait->sync->issue pipe, 2 CTAs/SM,
//      frag double-buffer, fused convert) + Q pre-scaled in convert +
//      conv transpose pad 68->65 (8-way -> 2-way bank conflicts).

namespace {
constexpr int BN = 8, S_ = 2048, D_ = 1024;
constexpr float SCALE = 0.03125f;          // D^-0.5 (folded into Q convert)
constexpr float NEGV  = -1000000000.0f;

constexpr int TM = 128, TN = 128, TK = 64;
constexpr int NT = 128;                                  // threads per CTA
constexpr uint32_t BUF_B   = 16384;                      // one 128x64 fp16 tile
constexpr uint32_t STAGE_B = 2 * BUF_B;                  // A,B
constexpr uint32_t PIPE_B  = 3 * STAGE_B;                // 98304
constexpr uint32_t SMEM_G1 = PIPE_B + 512 + 1024;        // + mask row + rowsum buf
constexpr uint32_t SMEM_G2 = PIPE_B + 512;               // + inv row buf
}  // namespace

// ------------------------- scratch (device globals) -------------------------
__device__ __align__(128) __half g_qh[(size_t)BN * S_ * D_];
__device__ __align__(128) __half g_kh[(size_t)BN * S_ * D_];
__device__ __align__(128) __half g_vt[(size_t)BN * D_ * S_];   // V^T [b][d][s]
__device__ __align__(128) __half g_p [(size_t)BN * S_ * S_];   // unnormalized exp P~
__device__ __align__(128) float  g_ps[(size_t)BN * S_ * 16];   // row partial sums

// ------------------------------- helpers ------------------------------------
__device__ __forceinline__ uint32_t smem_u32(const void* p) {
    uint32_t a;
    asm("{ .reg .u64 t; cvta.to.shared.u64 t, %1; cvt.u32.u64 %0, t; }"
        : "=r"(a) : "l"(p));
    return a;
}

#define LDSM4(r, addr) \
    asm volatile("ldmatrix.sync.aligned.m8n8.x4.shared.b16 {%0,%1,%2,%3}, [%4];" \
        : "=r"((r)[0]), "=r"((r)[1]), "=r"((r)[2]), "=r"((r)[3]) : "r"(addr))

#define MMA_F16(d, a, b0, b1) \
    asm volatile("mma.sync.aligned.m16n8k16.row.col.f32.f16.f16.f32 " \
        "{%0,%1,%2,%3}, {%4,%5,%6,%7}, {%8,%9}, {%0,%1,%2,%3};" \
        : "+f"((d)[0]), "+f"((d)[1]), "+f"((d)[2]), "+f"((d)[3]) \
        : "r"((a)[0]), "r"((a)[1]), "r"((a)[2]), "r"((a)[3]), "r"(b0), "r"(b1))

#define CP_ASYNC16(dst, src) \
    asm volatile("cp.async.cg.shared.global [%0], [%1], 16;" :: "r"(dst), "l"(src))
#define CP_COMMIT()  asm volatile("cp.async.commit_group;" ::: "memory")
#define CP_WAIT(n)   asm volatile("cp.async.wait_group %0;" :: "n"(n) : "memory")

__device__ __forceinline__ uint2 pack4(const uint16_t* h) {
    return make_uint2((uint32_t)h[0] | ((uint32_t)h[1] << 16),
                      (uint32_t)h[2] | ((uint32_t)h[3] << 16));
}

// --------------------------- fused convert kernel ----------------------------
// blocks [0,16384): Q*SCALE -> fp16 ; [16384,32768): K -> fp16 ;
// [32768,36864): V[b][s][d] -> V^T[b][d][s] fp16.
__global__ void __launch_bounds__(256) conv_all_kernel(
    const float* __restrict__ q, const float* __restrict__ k,
    const float* __restrict__ v) {
    __shared__ float tile[64][65];
    const int bx = blockIdx.x;
    const int tid = threadIdx.x;

    if (bx < 32768) {
        const bool isq = (bx < 16384);
        const float* src = isq ? q : k;
        __half* dst = isq ? g_qh : g_kh;
        const float sc = isq ? SCALE : 1.0f;
        size_t e0 = ((size_t)(bx & 16383) * 256 + tid) * 4;
        float4 val = *reinterpret_cast<const float4*>(src + e0);
        uint16_t h[4];
        h[0] = __half_as_ushort(__float2half_rn(val.x * sc));
        h[1] = __half_as_ushort(__float2half_rn(val.y * sc));
        h[2] = __half_as_ushort(__float2half_rn(val.z * sc));
        h[3] = __half_as_ushort(__float2half_rn(val.w * sc));
        *reinterpret_cast<uint2*>(dst + e0) = pack4(h);
        return;
    }

    const int id = bx - 32768;          // 0..4095
    const int b  = id >> 9;
    const int rest = id & 511;
    const int st = rest >> 4;           // s tile (0..31)
    const int dt = rest & 15;           // d tile (0..15)
    const int i0 = tid >> 4, j4 = (tid & 15) * 4;
#pragma unroll
    for (int r = 0; r < 4; ++r) {
        int i = i0 + r * 16;
        float4 val = *reinterpret_cast<const float4*>(
            v + ((size_t)b * S_ + st * 64 + i) * D_ + dt * 64 + j4);
        tile[i][j4 + 0] = val.x; tile[i][j4 + 1] = val.y;
        tile[i][j4 + 2] = val.z; tile[i][j4 + 3] = val.w;
    }
    __syncthreads();
#pragma unroll
    for (int r = 0; r < 4; ++r) {
        int dl_ = i0 + r * 16;
        uint16_t h[4];
#pragma unroll
        for (int c = 0; c < 4; ++c)
            h[c] = __half_as_ushort(__float2half_rn(tile[j4 + c][dl_]));
        size_t off = ((size_t)b * D_ + dt * 64 + dl_) * S_ + st * 64 + j4;
        *reinterpret_cast<uint2*>(g_vt + off) = pack4(h);
    }
}

// ------------------ GEMM1: P~ = exp(Q'K^T + mask) ----------------------------
__global__ void __launch_bounds__(NT, 2)
gemm1_kernel(const __half* __restrict__ Ah, const __half* __restrict__ Bh,
             const float* __restrict__ mask) {
    extern __shared__ __align__(1024) char smg[];
    const uint32_t smb = smem_u32(smg);
    float* smmask = (float*)(smg + PIPE_B);
    float (*smsum)[2] = (float(*)[2])(smg + PIPE_B + 512);  // [128][2]

    const int tid = threadIdx.x;
    const int mt = blockIdx.x, nt = blockIdx.y, b = blockIdx.z;
    const int warp = tid >> 5, lane = tid & 31;
    const int wm = warp & 1, wn = warp >> 1;   // 2x2 warp grid, 64x64 tiles
    const int lrow = lane & 15;
    const int lh16 = (lane >> 4) << 4;
    const int r7 = (lane & 7) << 4;
    constexpr int NC = D_ / TK;  // 16

    const int drow = tid >> 3, cc = tid & 7;
    const uint32_t dstoff0 = (uint32_t)(drow * 128 + ((cc ^ (drow & 7)) << 4));
    const __half* gA = Ah + ((size_t)b * S_ + mt * TM + drow) * D_ + cc * 8;
    const __half* gB = Bh + ((size_t)b * S_ + nt * TN + drow) * D_ + cc * 8;

    smmask[tid] = mask[(size_t)b * S_ + nt * TN + tid] * NEGV;

    uint32_t sload = 0;
    auto issue = [&]() {
        uint32_t da = smb + sload + dstoff0;
#pragma unroll
        for (int i = 0; i < 8; ++i) {
            CP_ASYNC16(da + i * 2048,         gA + i * 16 * D_);
            CP_ASYNC16(da + BUF_B + i * 2048, gB + i * 16 * D_);
        }
        CP_COMMIT();
        gA += TK; gB += TK;
        sload += STAGE_B; if (sload == PIPE_B) sload = 0;
    };

    float acc[4][8][4];
#pragma unroll
    for (int i = 0; i < 4; ++i)
#pragma unroll
        for (int n = 0; n < 8; ++n)
#pragma unroll
            for (int r = 0; r < 4; ++r) acc[i][n][r] = 0.f;

    issue();
    issue();

    const uint32_t cA = (uint32_t)((wm * 64 + lrow) * 128);
    const uint32_t cB = (uint32_t)(BUF_B + (wn * 64 + lrow) * 128);

    uint32_t scomp = 0;
#pragma unroll 1
    for (int c = 0; c < NC; ++c) {
        if (c + 1 < NC) CP_WAIT(1);
        else            CP_WAIT(0);
        __syncthreads();
        if (c + 2 < NC) issue();

        const uint32_t uA0 = smb + scomp + cA;
        const uint32_t uB0 = smb + scomp + cB;
        scomp += STAGE_B; if (scomp == PIPE_B) scomp = 0;

        // fragment double-buffer: prefetch ks+1 while issuing ks's MMAs
        uint32_t ah[2][4][4], bh[2][4][4];
        {
            const uint32_t kxr0 = (uint32_t)(lh16 ^ r7);
#pragma unroll
            for (int i = 0; i < 4; ++i) LDSM4(ah[0][i], uA0 + i * 2048 + kxr0);
#pragma unroll
            for (int j = 0; j < 4; ++j) LDSM4(bh[0][j], uB0 + j * 2048 + kxr0);
        }
#pragma unroll
        for (int ks = 0; ks < 4; ++ks) {
            const int cur = ks & 1, nxt = cur ^ 1;
            if (ks < 3) {
                const uint32_t kxr = (uint32_t)(((ks + 1) * 32 + lh16) ^ r7);
#pragma unroll
                for (int i = 0; i < 4; ++i)
                    LDSM4(ah[nxt][i], uA0 + i * 2048 + kxr);
#pragma unroll
                for (int j = 0; j < 4; ++j)
                    LDSM4(bh[nxt][j], uB0 + j * 2048 + kxr);
            }
#pragma unroll
            for (int i = 0; i < 4; ++i)
#pragma unroll
                for (int n = 0; n < 8; ++n) {
                    int j = n >> 1, s = n & 1;
                    MMA_F16(acc[i][n], ah[cur][i], bh[cur][j][s], bh[cur][j][s + 2]);
                }
        }
    }

    // ---- epilogue: e = exp(acc + mask), write fp16, reduce row sums ----
    const int rloc = wm * 64 + (lane >> 2);
    const int r0 = mt * TM + rloc;
    const int cl0 = wn * 64 + (lane & 3) * 2;
#pragma unroll
    for (int i = 0; i < 4; ++i) {
        float sum_lo = 0.f, sum_hi = 0.f;
#pragma unroll
        for (int n = 0; n < 8; ++n) {
            int cl = cl0 + n * 8;
            float mk0 = smmask[cl], mk1 = smmask[cl + 1];
            float e0 = __expf(acc[i][n][0] + mk0);
            float e1 = __expf(acc[i][n][1] + mk1);
            float e2 = __expf(acc[i][n][2] + mk0);
            float e3 = __expf(acc[i][n][3] + mk1);
            sum_lo += e0 + e1;
            sum_hi += e2 + e3;
            size_t rowa = (size_t)(b * S_ + r0 + i * 16) * S_ + nt * TN + cl;
            size_t rowb = rowa + (size_t)8 * S_;
            *reinterpret_cast<__half2*>(g_p + rowa) = __floats2half2_rn(e0, e1);
            *reinterpret_cast<__half2*>(g_p + rowb) = __floats2half2_rn(e2, e3);
        }
#pragma unroll
        for (int o = 1; o < 4; o <<= 1) {
            sum_lo += __shfl_xor_sync(~0u, sum_lo, o);
            sum_hi += __shfl_xor_sync(~0u, sum_hi, o);
        }
        if ((lane & 3) == 0) {
            smsum[rloc + i * 16][wn]     = sum_lo;
            smsum[rloc + i * 16 + 8][wn] = sum_hi;
        }
    }
    __syncthreads();
    {
        float s = smsum[tid][0] + smsum[tid][1];
        g_ps[((size_t)(b * S_ + mt * TM + tid)) * 16 + nt] = s;
    }
}

// ------------- GEMM2: out = (P~ @ V) * (1/rowsum)  (1-pass fp16) -------------
__global__ void __launch_bounds__(NT, 2)
gemm2_kernel(const __half* __restrict__ A, const __half* __restrict__ Bt,
             float* __restrict__ Cp) {
    extern __shared__ __align__(1024) char smg[];
    const uint32_t smb = smem_u32(smg);
    float* sminv = (float*)(smg + PIPE_B);  // [128]

    const int tid = threadIdx.x;
    const int mt = blockIdx.x, nt = blockIdx.y, b = blockIdx.z;
    const int warp = tid >> 5, lane = tid & 31;
    const int wm = warp & 1, wn = warp >> 1;
    const int lrow = lane & 15;
    const int lh16 = (lane >> 4) << 4;
    const int r7 = (lane & 7) << 4;
    constexpr int NC = S_ / TK;  // 32

    const int drow = tid >> 3, cc = tid & 7;
    const uint32_t dstoff0 = (uint32_t)(drow * 128 + ((cc ^ (drow & 7)) << 4));
    const __half* gA = A  + ((size_t)b * S_ + mt * TM + drow) * S_ + cc * 8;
    const __half* gB = Bt + ((size_t)b * D_ + nt * TN + drow) * S_ + cc * 8;

    {
        const float* ps = g_ps + ((size_t)(b * S_ + mt * TM + tid)) * 16;
        float s = 0.f;
#pragma unroll
        for (int j = 0; j < 16; ++j) s += ps[j];
        sminv[tid] = 1.0f / s;
    }

    uint32_t sload = 0;
    auto issue = [&]() {
        uint32_t da = smb + sload + dstoff0;
#pragma unroll
        for (int i = 0; i < 8; ++i) {
            CP_ASYNC16(da + i * 2048,         gA + i * 16 * S_);
            CP_ASYNC16(da + BUF_B + i * 2048, gB + i * 16 * S_);
        }
        CP_COMMIT();
        gA += TK; gB += TK;
        sload += STAGE_B; if (sload == PIPE_B) sload = 0;
    };

    float acc[4][8][4];
#pragma unroll
    for (int i = 0; i < 4; ++i)
#pragma unroll
        for (int n = 0; n < 8; ++n)
#pragma unroll
            for (int r = 0; r < 4; ++r) acc[i][n][r] = 0.f;

    issue();
    issue();

    const uint32_t cA = (uint32_t)((wm * 64 + lrow) * 128);
    const uint32_t cB = (uint32_t)(BUF_B + (wn * 64 + lrow) * 128);

    uint32_t scomp = 0;
#pragma unroll 1
    for (int c = 0; c < NC; ++c) {
        if (c + 1 < NC) CP_WAIT(1);
        else            CP_WAIT(0);
        __syncthreads();
        if (c + 2 < NC) issue();

        const uint32_t uA0 = smb + scomp + cA;
        const uint32_t uB0 = smb + scomp + cB;
        scomp += STAGE_B; if (scomp == PIPE_B) scomp = 0;

        uint32_t ah[2][4][4], bh[2][4][4];
        {
            const uint32_t kxr0 = (uint32_t)(lh16 ^ r7);
#pragma unroll
            for (int i = 0; i < 4; ++i) LDSM4(ah[0][i], uA0 + i * 2048 + kxr0);
#pragma unroll
            for (int j = 0; j < 4; ++j) LDSM4(bh[0][j], uB0 + j * 2048 + kxr0);
        }
#pragma unroll
        for (int ks = 0; ks < 4; ++ks) {
            const int cur = ks & 1, nxt = cur ^ 1;
            if (ks < 3) {
                const uint32_t kxr = (uint32_t)(((ks + 1) * 32 + lh16) ^ r7);
#pragma unroll
                for (int i = 0; i < 4; ++i)
                    LDSM4(ah[nxt][i], uA0 + i * 2048 + kxr);
#pragma unroll
                for (int j = 0; j < 4; ++j)
                    LDSM4(bh[nxt][j], uB0 + j * 2048 + kxr);
            }
#pragma unroll
            for (int i = 0; i < 4; ++i)
#pragma unroll
                for (int n = 0; n < 8; ++n) {
                    int j = n >> 1, s = n & 1;
                    MMA_F16(acc[i][n], ah[cur][i], bh[cur][j][s], bh[cur][j][s + 2]);
                }
        }
    }

    const int rloc = wm * 64 + (lane >> 2);
    const int r0 = mt * TM + rloc;
    const int cl0 = wn * 64 + (lane & 3) * 2;
#pragma unroll
    for (int i = 0; i < 4; ++i) {
        float inv_lo = sminv[rloc + i * 16];
        float inv_hi = sminv[rloc + i * 16 + 8];
#pragma unroll
        for (int n = 0; n < 8; ++n) {
            int col = nt * TN + cl0 + n * 8;
            size_t rowa = (size_t)(b * S_ + r0 + i * 16) * D_ + col;
            size_t rowb = rowa + (size_t)8 * D_;
            *reinterpret_cast<float2*>(Cp + rowa) =
                make_float2(acc[i][n][0] * inv_lo, acc[i][n][1] * inv_lo);
            *reinterpret_cast<float2*>(Cp + rowb) =
                make_float2(acc[i][n][2] * inv_hi, acc[i][n][3] * inv_hi);
        }
    }
}

// --------------------------------- launch -----------------------------------
extern "C" void kernel_launch(void* const* d_in, const int* in_sizes, int n_in,
                              void* d_out, int out_size) {
    const float* q    = (const float*)d_in[0];
    const float* k    = (const float*)d_in[1];
    const float* v    = (const float*)d_in[2];
    const float* mask = (const float*)d_in[3];
    float* out = (float*)d_out;

    cudaFuncSetAttribute(gemm1_kernel,
                         cudaFuncAttributeMaxDynamicSharedMemorySize, SMEM_G1);
    cudaFuncSetAttribute(gemm2_kernel,
                         cudaFuncAttributeMaxDynamicSharedMemorySize, SMEM_G2);

    __half *qh, *kh, *vt, *p;
    cudaGetSymbolAddress((void**)&qh, g_qh);
    cudaGetSymbolAddress((void**)&kh, g_kh);
    cudaGetSymbolAddress((void**)&vt, g_vt);
    cudaGetSymbolAddress((void**)&p,  g_p);

    conv_all_kernel<<<36864, 256>>>(q, k, v);

    gemm1_kernel<<<dim3(16, 16, 8), NT, SMEM_G1>>>(qh, kh, mask);
    gemm2_kernel<<<dim3(16, 8, 8), NT, SMEM_G2>>>(p, vt, out);
}

// round 14
// speedup vs baseline: 1.1293x; 1.0090x over previous
#include <cuda_runtime.h>
#include <cuda_fp16.h>
#include <cstdint>

// ScaledDotProductAttention B=8, S=2048, D=1024 fp32.
// HMMA fp16 1-pass both GEMMs; fused exp epilogue + fused 1/rowsum normalization.
// R14: R13 base + V-transpose folded into gemm1's grid as extra CTAs (overlap
//      with tensor-bound GEMM work) + vectorized Q/K convert (8 elem/thread).

namespace {
constexpr int BN = 8, S_ = 2048, D_ = 1024;
constexpr float SCALE = 0.03125f;          // D^-0.5 (folded into Q convert)
constexpr float NEGV  = -1000000000.0f;

constexpr int TM = 128, TN = 128, TK = 64;
constexpr int NT = 128;                                  // threads per CTA
constexpr uint32_t BUF_B   = 16384;                      // one 128x64 fp16 tile
constexpr uint32_t STAGE_B = 2 * BUF_B;                  // A,B
constexpr uint32_t PIPE_B  = 3 * STAGE_B;                // 98304
constexpr uint32_t SMEM_G1 = PIPE_B + 512 + 1024;        // + mask row + rowsum buf
constexpr uint32_t SMEM_G2 = PIPE_B + 512;               // + inv row buf
}  // namespace

// ------------------------- scratch (device globals) -------------------------
__device__ __align__(128) __half g_qh[(size_t)BN * S_ * D_];
__device__ __align__(128) __half g_kh[(size_t)BN * S_ * D_];
__device__ __align__(128) __half g_vt[(size_t)BN * D_ * S_];   // V^T [b][d][s]
__device__ __align__(128) __half g_p [(size_t)BN * S_ * S_];   // unnormalized exp P~
__device__ __align__(128) float  g_ps[(size_t)BN * S_ * 16];   // row partial sums

// ------------------------------- helpers ------------------------------------
__device__ __forceinline__ uint32_t smem_u32(const void* p) {
    uint32_t a;
    asm("{ .reg .u64 t; cvta.to.shared.u64 t, %1; cvt.u32.u64 %0, t; }"
        : "=r"(a) : "l"(p));
    return a;
}

#define LDSM4(r, addr) \
    asm volatile("ldmatrix.sync.aligned.m8n8.x4.shared.b16 {%0,%1,%2,%3}, [%4];" \
        : "=r"((r)[0]), "=r"((r)[1]), "=r"((r)[2]), "=r"((r)[3]) : "r"(addr))

#define MMA_F16(d, a, b0, b1) \
    asm volatile("mma.sync.aligned.m16n8k16.row.col.f32.f16.f16.f32 " \
        "{%0,%1,%2,%3}, {%4,%5,%6,%7}, {%8,%9}, {%0,%1,%2,%3};" \
        : "+f"((d)[0]), "+f"((d)[1]), "+f"((d)[2]), "+f"((d)[3]) \
        : "r"((a)[0]), "r"((a)[1]), "r"((a)[2]), "r"((a)[3]), "r"(b0), "r"(b1))

#define CP_ASYNC16(dst, src) \
    asm volatile("cp.async.cg.shared.global [%0], [%1], 16;" :: "r"(dst), "l"(src))
#define CP_COMMIT()  asm volatile("cp.async.commit_group;" ::: "memory")
#define CP_WAIT(n)   asm volatile("cp.async.wait_group %0;" :: "n"(n) : "memory")

__device__ __forceinline__ uint2 pack4(const uint16_t* h) {
    return make_uint2((uint32_t)h[0] | ((uint32_t)h[1] << 16),
                      (uint32_t)h[2] | ((uint32_t)h[3] << 16));
}

// --------------------- convert kernel: Q*SCALE, K -> fp16 --------------------
// 8 elements per thread: 2x float4 load -> 1x uint4 store.
// blocks [0,8192): Q ; [8192,16384): K.
__global__ void __launch_bounds__(256) conv_qk_kernel(
    const float* __restrict__ q, const float* __restrict__ k) {
    const int bx = blockIdx.x;
    const bool isq = (bx < 8192);
    const float* src = isq ? q : k;
    __half* dst = isq ? g_qh : g_kh;
    const float sc = isq ? SCALE : 1.0f;
    size_t e0 = ((size_t)(bx & 8191) * 256 + threadIdx.x) * 8;
    float4 v0 = *reinterpret_cast<const float4*>(src + e0);
    float4 v1 = *reinterpret_cast<const float4*>(src + e0 + 4);
    uint16_t h[8];
    h[0] = __half_as_ushort(__float2half_rn(v0.x * sc));
    h[1] = __half_as_ushort(__float2half_rn(v0.y * sc));
    h[2] = __half_as_ushort(__float2half_rn(v0.z * sc));
    h[3] = __half_as_ushort(__float2half_rn(v0.w * sc));
    h[4] = __half_as_ushort(__float2half_rn(v1.x * sc));
    h[5] = __half_as_ushort(__float2half_rn(v1.y * sc));
    h[6] = __half_as_ushort(__float2half_rn(v1.z * sc));
    h[7] = __half_as_ushort(__float2half_rn(v1.w * sc));
    uint2 lo = pack4(h), hi = pack4(h + 4);
    *reinterpret_cast<uint4*>(dst + e0) = make_uint4(lo.x, lo.y, hi.x, hi.y);
}

// ------------------ GEMM1: P~ = exp(Q'K^T + mask) ----------------------------
// Grid (20,16,8): mt<16 -> GEMM tile; mt>=16 -> V-transpose CTAs (overlapped).
__global__ void __launch_bounds__(NT, 2)
gemm1_kernel(const __half* __restrict__ Ah, const __half* __restrict__ Bh,
             const float* __restrict__ mask, const float* __restrict__ v) {
    extern __shared__ __align__(1024) char smg[];

    const int tid = threadIdx.x;
    const int mt = blockIdx.x, nt = blockIdx.y, b = blockIdx.z;

    if (mt >= 16) {
        // ---- V[b][s][d] -> V^T[b][d][s], 8 tiles of 64x64 per CTA ----
        float (*tile)[65] = (float(*)[65])smg;
        const int rest0 = (mt - 16) * 16 + nt;   // 0..63
        const int i0 = tid >> 4, j4 = (tid & 15) * 4;
#pragma unroll 1
        for (int u = 0; u < 8; ++u) {
            const int rest = rest0 * 8 + u;      // 0..511
            const int st = rest >> 4;            // s tile (0..31)
            const int dt = rest & 15;            // d tile (0..15)
#pragma unroll
            for (int r = 0; r < 8; ++r) {
                int i = i0 + r * 8;
                float4 val = *reinterpret_cast<const float4*>(
                    v + ((size_t)b * S_ + st * 64 + i) * D_ + dt * 64 + j4);
                tile[i][j4 + 0] = val.x; tile[i][j4 + 1] = val.y;
                tile[i][j4 + 2] = val.z; tile[i][j4 + 3] = val.w;
            }
            __syncthreads();
#pragma unroll
            for (int r = 0; r < 8; ++r) {
                int dl_ = i0 + r * 8;
                uint16_t h[4];
#pragma unroll
                for (int c = 0; c < 4; ++c)
                    h[c] = __half_as_ushort(__float2half_rn(tile[j4 + c][dl_]));
                size_t off = ((size_t)b * D_ + dt * 64 + dl_) * S_ + st * 64 + j4;
                *reinterpret_cast<uint2*>(g_vt + off) = pack4(h);
            }
            __syncthreads();
        }
        return;
    }

    const uint32_t smb = smem_u32(smg);
    float* smmask = (float*)(smg + PIPE_B);
    float (*smsum)[2] = (float(*)[2])(smg + PIPE_B + 512);  // [128][2]

    const int warp = tid >> 5, lane = tid & 31;
    const int wm = warp & 1, wn = warp >> 1;   // 2x2 warp grid, 64x64 tiles
    const int lrow = lane & 15;
    const int lh16 = (lane >> 4) << 4;
    const int r7 = (lane & 7) << 4;
    constexpr int NC = D_ / TK;  // 16

    const int drow = tid >> 3, cc = tid & 7;
    const uint32_t dstoff0 = (uint32_t)(drow * 128 + ((cc ^ (drow & 7)) << 4));
    const __half* gA = Ah + ((size_t)b * S_ + mt * TM + drow) * D_ + cc * 8;
    const __half* gB = Bh + ((size_t)b * S_ + nt * TN + drow) * D_ + cc * 8;

    smmask[tid] = mask[(size_t)b * S_ + nt * TN + tid] * NEGV;

    uint32_t sload = 0;
    auto issue = [&]() {
        uint32_t da = smb + sload + dstoff0;
#pragma unroll
        for (int i = 0; i < 8; ++i) {
            CP_ASYNC16(da + i * 2048,         gA + i * 16 * D_);
            CP_ASYNC16(da + BUF_B + i * 2048, gB + i * 16 * D_);
        }
        CP_COMMIT();
        gA += TK; gB += TK;
        sload += STAGE_B; if (sload == PIPE_B) sload = 0;
    };

    float acc[4][8][4];
#pragma unroll
    for (int i = 0; i < 4; ++i)
#pragma unroll
        for (int n = 0; n < 8; ++n)
#pragma unroll
            for (int r = 0; r < 4; ++r) acc[i][n][r] = 0.f;

    issue();
    issue();

    const uint32_t cA = (uint32_t)((wm * 64 + lrow) * 128);
    const uint32_t cB = (uint32_t)(BUF_B + (wn * 64 + lrow) * 128);

    uint32_t scomp = 0;
#pragma unroll 1
    for (int c = 0; c < NC; ++c) {
        if (c + 1 < NC) CP_WAIT(1);
        else            CP_WAIT(0);
        __syncthreads();
        if (c + 2 < NC) issue();

        const uint32_t uA0 = smb + scomp + cA;
        const uint32_t uB0 = smb + scomp + cB;
        scomp += STAGE_B; if (scomp == PIPE_B) scomp = 0;

        // fragment double-buffer: prefetch ks+1 while issuing ks's MMAs
        uint32_t ah[2][4][4], bh[2][4][4];
        {
            const uint32_t kxr0 = (uint32_t)(lh16 ^ r7);
#pragma unroll
            for (int i = 0; i < 4; ++i) LDSM4(ah[0][i], uA0 + i * 2048 + kxr0);
#pragma unroll
            for (int j = 0; j < 4; ++j) LDSM4(bh[0][j], uB0 + j * 2048 + kxr0);
        }
#pragma unroll
        for (int ks = 0; ks < 4; ++ks) {
            const int cur = ks & 1, nxt = cur ^ 1;
            if (ks < 3) {
                const uint32_t kxr = (uint32_t)(((ks + 1) * 32 + lh16) ^ r7);
#pragma unroll
                for (int i = 0; i < 4; ++i)
                    LDSM4(ah[nxt][i], uA0 + i * 2048 + kxr);
#pragma unroll
                for (int j = 0; j < 4; ++j)
                    LDSM4(bh[nxt][j], uB0 + j * 2048 + kxr);
            }
#pragma unroll
            for (int i = 0; i < 4; ++i)
#pragma unroll
                for (int n = 0; n < 8; ++n) {
                    int j = n >> 1, s = n & 1;
                    MMA_F16(acc[i][n], ah[cur][i], bh[cur][j][s], bh[cur][j][s + 2]);
                }
        }
    }

    // ---- epilogue: e = exp(acc + mask), write fp16, reduce row sums ----
    const int rloc = wm * 64 + (lane >> 2);
    const int r0 = mt * TM + rloc;
    const int cl0 = wn * 64 + (lane & 3) * 2;
#pragma unroll
    for (int i = 0; i < 4; ++i) {
        float sum_lo = 0.f, sum_hi = 0.f;
#pragma unroll
        for (int n = 0; n < 8; ++n) {
            int cl = cl0 + n * 8;
            float mk0 = smmask[cl], mk1 = smmask[cl + 1];
            float e0 = __expf(acc[i][n][0] + mk0);
            float e1 = __expf(acc[i][n][1] + mk1);
            float e2 = __expf(acc[i][n][2] + mk0);
            float e3 = __expf(acc[i][n][3] + mk1);
            sum_lo += e0 + e1;
            sum_hi += e2 + e3;
            size_t rowa = (size_t)(b * S_ + r0 + i * 16) * S_ + nt * TN + cl;
            size_t rowb = rowa + (size_t)8 * S_;
            *reinterpret_cast<__half2*>(g_p + rowa) = __floats2half2_rn(e0, e1);
            *reinterpret_cast<__half2*>(g_p + rowb) = __floats2half2_rn(e2, e3);
        }
#pragma unroll
        for (int o = 1; o < 4; o <<= 1) {
            sum_lo += __shfl_xor_sync(~0u, sum_lo, o);
            sum_hi += __shfl_xor_sync(~0u, sum_hi, o);
        }
        if ((lane & 3) == 0) {
            smsum[rloc + i * 16][wn]     = sum_lo;
            smsum[rloc + i * 16 + 8][wn] = sum_hi;
        }
    }
    __syncthreads();
    {
        float s = smsum[tid][0] + smsum[tid][1];
        g_ps[((size_t)(b * S_ + mt * TM + tid)) * 16 + nt] = s;
    }
}

// ------------- GEMM2: out = (P~ @ V) * (1/rowsum)  (1-pass fp16) -------------
__global__ void __launch_bounds__(NT, 2)
gemm2_kernel(const __half* __restrict__ A, const __half* __restrict__ Bt,
             float* __restrict__ Cp) {
    extern __shared__ __align__(1024) char smg[];
    const uint32_t smb = smem_u32(smg);
    float* sminv = (float*)(smg + PIPE_B);  // [128]

    const int tid = threadIdx.x;
    const int mt = blockIdx.x, nt = blockIdx.y, b = blockIdx.z;
    const int warp = tid >> 5, lane = tid & 31;
    const int wm = warp & 1, wn = warp >> 1;
    const int lrow = lane & 15;
    const int lh16 = (lane >> 4) << 4;
    const int r7 = (lane & 7) << 4;
    constexpr int NC = S_ / TK;  // 32

    const int drow = tid >> 3, cc = tid & 7;
    const uint32_t dstoff0 = (uint32_t)(drow * 128 + ((cc ^ (drow & 7)) << 4));
    const __half* gA = A  + ((size_t)b * S_ + mt * TM + drow) * S_ + cc * 8;
    const __half* gB = Bt + ((size_t)b * D_ + nt * TN + drow) * S_ + cc * 8;

    {
        const float* ps = g_ps + ((size_t)(b * S_ + mt * TM + tid)) * 16;
        float s = 0.f;
#pragma unroll
        for (int j = 0; j < 16; ++j) s += ps[j];
        sminv[tid] = 1.0f / s;
    }

    uint32_t sload = 0;
    auto issue = [&]() {
        uint32_t da = smb + sload + dstoff0;
#pragma unroll
        for (int i = 0; i < 8; ++i) {
            CP_ASYNC16(da + i * 2048,         gA + i * 16 * S_);
            CP_ASYNC16(da + BUF_B + i * 2048, gB + i * 16 * S_);
        }
        CP_COMMIT();
        gA += TK; gB += TK;
        sload += STAGE_B; if (sload == PIPE_B) sload = 0;
    };

    float acc[4][8][4];
#pragma unroll
    for (int i = 0; i < 4; ++i)
#pragma unroll
        for (int n = 0; n < 8; ++n)
#pragma unroll
            for (int r = 0; r < 4; ++r) acc[i][n][r] = 0.f;

    issue();
    issue();

    const uint32_t cA = (uint32_t)((wm * 64 + lrow) * 128);
    const uint32_t cB = (uint32_t)(BUF_B + (wn * 64 + lrow) * 128);

    uint32_t scomp = 0;
#pragma unroll 1
    for (int c = 0; c < NC; ++c) {
        if (c + 1 < NC) CP_WAIT(1);
        else            CP_WAIT(0);
        __syncthreads();
        if (c + 2 < NC) issue();

        const uint32_t uA0 = smb + scomp + cA;
        const uint32_t uB0 = smb + scomp + cB;
        scomp += STAGE_B; if (scomp == PIPE_B) scomp = 0;

        uint32_t ah[2][4][4], bh[2][4][4];
        {
            const uint32_t kxr0 = (uint32_t)(lh16 ^ r7);
#pragma unroll
            for (int i = 0; i < 4; ++i) LDSM4(ah[0][i], uA0 + i * 2048 + kxr0);
#pragma unroll
            for (int j = 0; j < 4; ++j) LDSM4(bh[0][j], uB0 + j * 2048 + kxr0);
        }
#pragma unroll
        for (int ks = 0; ks < 4; ++ks) {
            const int cur = ks & 1, nxt = cur ^ 1;
            if (ks < 3) {
                const uint32_t kxr = (uint32_t)(((ks + 1) * 32 + lh16) ^ r7);
#pragma unroll
                for (int i = 0; i < 4; ++i)
                    LDSM4(ah[nxt][i], uA0 + i * 2048 + kxr);
#pragma unroll
                for (int j = 0; j < 4; ++j)
                    LDSM4(bh[nxt][j], uB0 + j * 2048 + kxr);
            }
#pragma unroll
            for (int i = 0; i < 4; ++i)
#pragma unroll
                for (int n = 0; n < 8; ++n) {
                    int j = n >> 1, s = n & 1;
                    MMA_F16(acc[i][n], ah[cur][i], bh[cur][j][s], bh[cur][j][s + 2]);
                }
        }
    }

    const int rloc = wm * 64 + (lane >> 2);
    const int r0 = mt * TM + rloc;
    const int cl0 = wn * 64 + (lane & 3) * 2;
#pragma unroll
    for (int i = 0; i < 4; ++i) {
        float inv_lo = sminv[rloc + i * 16];
        float inv_hi = sminv[rloc + i * 16 + 8];
#pragma unroll
        for (int n = 0; n < 8; ++n) {
            int col = nt * TN + cl0 + n * 8;
            size_t rowa = (size_t)(b * S_ + r0 + i * 16) * D_ + col;
            size_t rowb = rowa + (size_t)8 * D_;
            *reinterpret_cast<float2*>(Cp + rowa) =
                make_float2(acc[i][n][0] * inv_lo, acc[i][n][1] * inv_lo);
            *reinterpret_cast<float2*>(Cp + rowb) =
                make_float2(acc[i][n][2] * inv_hi, acc[i][n][3] * inv_hi);
        }
    }
}

// --------------------------------- launch -----------------------------------
extern "C" void kernel_launch(void* const* d_in, const int* in_sizes, int n_in,
                              void* d_out, int out_size) {
    const float* q    = (const float*)d_in[0];
    const float* k    = (const float*)d_in[1];
    const float* v    = (const float*)d_in[2];
    const float* mask = (const float*)d_in[3];
    float* out = (float*)d_out;

    cudaFuncSetAttribute(gemm1_kernel,
                         cudaFuncAttributeMaxDynamicSharedMemorySize, SMEM_G1);
    cudaFuncSetAttribute(gemm2_kernel,
                         cudaFuncAttributeMaxDynamicSharedMemorySize, SMEM_G2);

    __half *qh, *kh, *vt, *p;
    cudaGetSymbolAddress((void**)&qh, g_qh);
    cudaGetSymbolAddress((void**)&kh, g_kh);
    cudaGetSymbolAddress((void**)&vt, g_vt);
    cudaGetSymbolAddress((void**)&p,  g_p);

    conv_qk_kernel<<<16384, 256>>>(q, k);

    gemm1_kernel<<<dim3(20, 16, 8), NT, SMEM_G1>>>(qh, kh, mask, v);
    gemm2_kernel<<<dim3(16, 8, 8), NT, SMEM_G2>>>(p, vt, out);
}